// round 3
// baseline (speedup 1.0000x reference)
#include <cuda_runtime.h>
#include <cuda_bf16.h>

// Problem: B=4, L=2048, H=8, D=64.
// Reference math collapses: out[b,q,h,d] = (sum_w softmax(...)[b,q,w,h]) * (sum_e V[b,e,h,d])
//                                        = 1 * sum_l V[b,l,h,d]
// Q and K are unused. We compute the column-sum of V over L and broadcast over q.

#define B_DIM 4
#define L_DIM 2048
#define HD 512            // H*D = 8*64 floats per (b, l)
#define CHUNKS 64         // L split into 64 chunks of 32 rows
#define ROWS_PER_CHUNK 32

// Scratch (allocation-free: __device__ globals)
__device__ float g_partial[B_DIM * CHUNKS * HD];   // 512 KB
__device__ float g_vsum[B_DIM * HD];               // 8 KB

// Stage 1: partial sums over 32 rows each. Fully coalesced: thread t reads
// V[b, row, t] — consecutive t -> consecutive addresses, 2 KB per row.
__global__ void __launch_bounds__(HD) vpartial_kernel(const float* __restrict__ V) {
    const int b = blockIdx.y;
    const int chunk = blockIdx.x;
    const int t = threadIdx.x;
    const float* base = V + ((size_t)b * L_DIM + (size_t)chunk * ROWS_PER_CHUNK) * HD + t;
    float s = 0.0f;
#pragma unroll
    for (int i = 0; i < ROWS_PER_CHUNK; ++i) {
        s += __ldg(base + (size_t)i * HD);
    }
    g_partial[((size_t)b * CHUNKS + chunk) * HD + t] = s;
}

// Stage 2: reduce the 64 chunk-partials per (b, t). Tiny, L2-resident.
__global__ void __launch_bounds__(HD) vsum_kernel() {
    const int b = blockIdx.x;
    const int t = threadIdx.x;
    float s = 0.0f;
#pragma unroll
    for (int c = 0; c < CHUNKS; ++c) {
        s += g_partial[((size_t)b * CHUNKS + c) * HD + t];
    }
    g_vsum[b * HD + t] = s;
}

// Stage 3: broadcast vsum over the q axis. One float4 (STG.128) per thread.
// Per-b row of output is 128 float4; vsum table is 8 KB (L1-resident).
__global__ void __launch_bounds__(256) bcast_kernel(float4* __restrict__ out) {
    const float4* __restrict__ vsum4 = reinterpret_cast<const float4*>(g_vsum);
    const unsigned gid = blockIdx.x * 256u + threadIdx.x;   // 0 .. B*L*128 - 1
    const unsigned b = gid >> 18;                            // / (L_DIM * 128)
    const unsigned j = gid & 127u;                           // float4 index within (b,q) row
    out[gid] = __ldg(&vsum4[b * 128u + j]);
}

extern "C" void kernel_launch(void* const* d_in, const int* in_sizes, int n_in,
                              void* d_out, int out_size) {
    // inputs: [0] queries, [1] keys, [2] values (all float32). Q, K are unused by the math.
    const float* V = (const float*)d_in[2];
    float* out = (float*)d_out;

    dim3 g1(CHUNKS, B_DIM);
    vpartial_kernel<<<g1, HD>>>(V);
    vsum_kernel<<<B_DIM, HD>>>();

    const unsigned total_f4 = (unsigned)B_DIM * L_DIM * (HD / 4);  // 1,048,576
    bcast_kernel<<<total_f4 / 256, 256>>>(reinterpret_cast<float4*>(out));
}